// round 3
// baseline (speedup 1.0000x reference)
#include <cuda_runtime.h>
#include <cfloat>

// Problem constants
#define NPTS    65536
#define KNB     32
#define CNT_INV (1.0f / 2097152.0f)   // 1/(N*K), exact power of two
#define BN_EPS  1e-5f

// ---------------- scratch (__device__ globals: no allocation allowed) ----------------
__device__ float g_sL[32], g_qL[32], g_sF[32], g_qF[32];   // layer1 pre-BN channel stats
__device__ float g_wl[32 * 3];                              // folded layer1 xyz weights
__device__ float g_wf[32 * 16];                             // folded layer1 feat weights
__device__ float g_bh[32];                                  // folded layer1 bias
__device__ float g_s2[64], g_q2[64];                        // layer2 pre-BN channel stats
__device__ float g_zmax[NPTS * 64];                         // per-(n,o) max_k z  (pre-BN)
__device__ float g_zmin[NPTS * 64];                         // per-(n,o) min_k z  (pre-BN)

// ---------------- packed f32x2 FMA (guarded: sm_100+ only, scalar fallback) ----------------
__device__ __forceinline__ void ffma2(float2& acc, float2 a, float2 b) {
#if defined(__CUDA_ARCH__) && (__CUDA_ARCH__ >= 1000)
    union F2U { float2 f; unsigned long long u; };
    F2U A, B, C; A.f = a; B.f = b; C.f = acc;
    asm("fma.rn.f32x2 %0, %1, %2, %0;" : "+l"(C.u) : "l"(A.u), "l"(B.u));
    acc = C.f;
#else
    acc.x = fmaf(a.x, b.x, acc.x);
    acc.y = fmaf(a.y, b.y, acc.y);
#endif
}

// ---------------- kernel 0: zero the stat accumulators (fresh every launch) ----------------
__global__ void k_init() {
    const int t = threadIdx.x;   // 64 threads
    if (t < 32) { g_sL[t] = 0.f; g_qL[t] = 0.f; g_sF[t] = 0.f; g_qF[t] = 0.f; }
    g_s2[t] = 0.f; g_q2[t] = 0.f;
}

// ---------------- kernel 1: layer-1 pre-BN channel statistics ----------------
// One warp processes points sequentially; lane = hidden channel o in [0,32).
// Inputs for each (n,k) sample are same-address broadcast loads (L2-resident).
__global__ __launch_bounds__(128)
void k_stats1(const float* __restrict__ xyz, const float* __restrict__ pts,
              const int* __restrict__ gidx,
              const float* __restrict__ Wl0, const float* __restrict__ Wf0) {
    const int lane  = threadIdx.x & 31;
    const int warp  = blockIdx.x * (blockDim.x >> 5) + (threadIdx.x >> 5);
    const int nwarp = gridDim.x * (blockDim.x >> 5);

    const float wl0 = Wl0[lane * 3 + 0];
    const float wl1 = Wl0[lane * 3 + 1];
    const float wl2 = Wl0[lane * 3 + 2];
    float wf[16];
#pragma unroll
    for (int c = 0; c < 16; c++) wf[c] = Wf0[lane * 16 + c];

    float sL = 0.f, qL = 0.f, sF = 0.f, qF = 0.f;

    for (int n = warp; n < NPTS; n += nwarp) {
        const int   gi = gidx[n * KNB + lane];          // coalesced
        const float c0 = __ldg(&xyz[n * 3 + 0]);
        const float c1 = __ldg(&xyz[n * 3 + 1]);
        const float c2 = __ldg(&xyz[n * 3 + 2]);
#pragma unroll 2
        for (int k = 0; k < KNB; k++) {
            const int g = __shfl_sync(0xffffffffu, gi, k);
            const float d0 = __ldg(&xyz[g * 3 + 0]) - c0;
            const float d1 = __ldg(&xyz[g * 3 + 1]) - c1;
            const float d2 = __ldg(&xyz[g * 3 + 2]) - c2;
            const float4* pr = (const float4*)pts + (size_t)g * 4;
            const float4 p0 = __ldg(pr + 0), p1 = __ldg(pr + 1);
            const float4 p2 = __ldg(pr + 2), p3 = __ldg(pr + 3);

            float loc = wl0 * d0; loc = fmaf(wl1, d1, loc); loc = fmaf(wl2, d2, loc);

            float ft = wf[0] * p0.x;
            ft = fmaf(wf[1],  p0.y, ft); ft = fmaf(wf[2],  p0.z, ft); ft = fmaf(wf[3],  p0.w, ft);
            ft = fmaf(wf[4],  p1.x, ft); ft = fmaf(wf[5],  p1.y, ft); ft = fmaf(wf[6],  p1.z, ft);
            ft = fmaf(wf[7],  p1.w, ft); ft = fmaf(wf[8],  p2.x, ft); ft = fmaf(wf[9],  p2.y, ft);
            ft = fmaf(wf[10], p2.z, ft); ft = fmaf(wf[11], p2.w, ft); ft = fmaf(wf[12], p3.x, ft);
            ft = fmaf(wf[13], p3.y, ft); ft = fmaf(wf[14], p3.z, ft); ft = fmaf(wf[15], p3.w, ft);

            sL += loc; qL = fmaf(loc, loc, qL);
            sF += ft;  qF = fmaf(ft,  ft,  qF);
        }
    }
    atomicAdd(&g_sL[lane], sL); atomicAdd(&g_qL[lane], qL);
    atomicAdd(&g_sF[lane], sF); atomicAdd(&g_qF[lane], qF);
}

// ---------------- kernel 2: fold BN1 into layer-1 weights ----------------
__global__ void k_fold(const float* __restrict__ Wl0, const float* __restrict__ gl0,
                       const float* __restrict__ bl0, const float* __restrict__ Wf0,
                       const float* __restrict__ gf0, const float* __restrict__ bf0) {
    const int i = threadIdx.x;
    if (i >= 32) return;
    const float mL = g_sL[i] * CNT_INV;
    const float vL = fmaxf(g_qL[i] * CNT_INV - mL * mL, 0.f);
    const float sL = gl0[i] * rsqrtf(vL + BN_EPS);
    const float mF = g_sF[i] * CNT_INV;
    const float vF = fmaxf(g_qF[i] * CNT_INV - mF * mF, 0.f);
    const float sF = gf0[i] * rsqrtf(vF + BN_EPS);
#pragma unroll
    for (int c = 0; c < 3; c++)  g_wl[i * 3 + c]  = sL * Wl0[i * 3 + c];
#pragma unroll
    for (int c = 0; c < 16; c++) g_wf[i * 16 + c] = sF * Wf0[i * 16 + c];
    g_bh[i] = bl0[i] - sL * mL + bf0[i] - sF * mF;
}

// ---------------- kernel 3: main fused pass ----------------
// One warp per point n. Layer 1: lane = hidden channel i (folded weights in
// registers, neighbor data broadcast). Layer 2: lane = output channels
// (lane, lane+32) with packed f32x2 FMA over hidden-channel pairs via shuffles.
// Stores per-(n,o) zmax/zmin (pre-BN2), accumulates global sum / sumsq of z.
__global__ __launch_bounds__(128, 4)
void k_main(const float* __restrict__ xyz, const float* __restrict__ pts,
            const int* __restrict__ gidx, const float* __restrict__ W1) {
    const int lane  = threadIdx.x & 31;
    const int warp  = blockIdx.x * (blockDim.x >> 5) + (threadIdx.x >> 5);
    const int nwarp = gridDim.x * (blockDim.x >> 5);

    // layer-1 folded weights, lane = hidden channel
    const float wl0 = g_wl[lane * 3 + 0];
    const float wl1 = g_wl[lane * 3 + 1];
    const float wl2 = g_wl[lane * 3 + 2];
    float wf[16];
#pragma unroll
    for (int c = 0; c < 16; c++) wf[c] = g_wf[lane * 16 + c];
    const float bh = g_bh[lane];

    // layer-2 weights, lane = (o, o+32), packed over hidden-channel pairs
    float2 wA[16], wB[16];
    {
        const float2* rA = (const float2*)(W1 + lane * 32);
        const float2* rB = (const float2*)(W1 + (lane + 32) * 32);
#pragma unroll
        for (int t = 0; t < 16; t++) { wA[t] = __ldg(rA + t); wB[t] = __ldg(rB + t); }
    }

    float sumA = 0.f, sqA = 0.f, sumB = 0.f, sqB = 0.f;

    for (int n = warp; n < NPTS; n += nwarp) {
        const int   gi = gidx[n * KNB + lane];          // coalesced
        const float c0 = __ldg(&xyz[n * 3 + 0]);
        const float c1 = __ldg(&xyz[n * 3 + 1]);
        const float c2 = __ldg(&xyz[n * 3 + 2]);

        float maxA = -FLT_MAX, minA = FLT_MAX, maxB = -FLT_MAX, minB = FLT_MAX;

#pragma unroll 2
        for (int k = 0; k < KNB; k++) {
            const int g = __shfl_sync(0xffffffffu, gi, k);
            const float d0 = __ldg(&xyz[g * 3 + 0]) - c0;
            const float d1 = __ldg(&xyz[g * 3 + 1]) - c1;
            const float d2 = __ldg(&xyz[g * 3 + 2]) - c2;
            const float4* pr = (const float4*)pts + (size_t)g * 4;
            const float4 p0 = __ldg(pr + 0), p1 = __ldg(pr + 1);
            const float4 p2 = __ldg(pr + 2), p3 = __ldg(pr + 3);

            float h = bh;
            h = fmaf(wl0, d0, h); h = fmaf(wl1, d1, h); h = fmaf(wl2, d2, h);
            h = fmaf(wf[0],  p0.x, h); h = fmaf(wf[1],  p0.y, h);
            h = fmaf(wf[2],  p0.z, h); h = fmaf(wf[3],  p0.w, h);
            h = fmaf(wf[4],  p1.x, h); h = fmaf(wf[5],  p1.y, h);
            h = fmaf(wf[6],  p1.z, h); h = fmaf(wf[7],  p1.w, h);
            h = fmaf(wf[8],  p2.x, h); h = fmaf(wf[9],  p2.y, h);
            h = fmaf(wf[10], p2.z, h); h = fmaf(wf[11], p2.w, h);
            h = fmaf(wf[12], p3.x, h); h = fmaf(wf[13], p3.y, h);
            h = fmaf(wf[14], p3.z, h); h = fmaf(wf[15], p3.w, h);
            h = fmaxf(h, 0.f);                           // ReLU(BN1(loc)+BN1(feat))

            // layer 2: z[o] = sum_i W1[o][i] * h[i]  (b1 cancels inside BN2)
            float2 zA = make_float2(0.f, 0.f);
            float2 zB = make_float2(0.f, 0.f);
#pragma unroll
            for (int t = 0; t < 16; t++) {
                float2 hv;
                hv.x = __shfl_sync(0xffffffffu, h, 2 * t);
                hv.y = __shfl_sync(0xffffffffu, h, 2 * t + 1);
                ffma2(zA, wA[t], hv);
                ffma2(zB, wB[t], hv);
            }
            const float za = zA.x + zA.y;
            const float zb = zB.x + zB.y;

            maxA = fmaxf(maxA, za); minA = fminf(minA, za);
            maxB = fmaxf(maxB, zb); minB = fminf(minB, zb);
            sumA += za; sqA = fmaf(za, za, sqA);
            sumB += zb; sqB = fmaf(zb, zb, sqB);
        }

        g_zmax[n * 64 + lane]      = maxA;
        g_zmax[n * 64 + 32 + lane] = maxB;
        g_zmin[n * 64 + lane]      = minA;
        g_zmin[n * 64 + 32 + lane] = minB;
    }

    atomicAdd(&g_s2[lane],      sumA); atomicAdd(&g_q2[lane],      sqA);
    atomicAdd(&g_s2[lane + 32], sumB); atomicAdd(&g_q2[lane + 32], sqB);
}

// ---------------- kernel 4: finalize ----------------
// out[n,o] = relu(s2*(z* - m2) + beta2), z* = (s2>=0 ? zmax : zmin)  (monotone trick)
__global__ __launch_bounds__(256)
void k_final(const float* __restrict__ g1, const float* __restrict__ beta1,
             float* __restrict__ out) {
    const int idx = blockIdx.x * blockDim.x + threadIdx.x;
    if (idx >= NPTS * 64) return;
    const int o = idx & 63;
    const float m = g_s2[o] * CNT_INV;
    const float v = fmaxf(g_q2[o] * CNT_INV - m * m, 0.f);
    const float s = g1[o] * rsqrtf(v + BN_EPS);
    const float c = beta1[o] - s * m;
    const float z = (s >= 0.f) ? g_zmax[idx] : g_zmin[idx];
    out[idx] = fmaxf(fmaf(s, z, c), 0.f);
}

// ---------------- launch ----------------
extern "C" void kernel_launch(void* const* d_in, const int* in_sizes, int n_in,
                              void* d_out, int out_size) {
    const float* xyz   = (const float*)d_in[0];
    const float* pts   = (const float*)d_in[1];
    const int*   gidx  = (const int*)  d_in[2];
    const float* Wl0   = (const float*)d_in[3];
    const float* gl0   = (const float*)d_in[4];
    const float* bl0   = (const float*)d_in[5];
    const float* Wf0   = (const float*)d_in[6];
    const float* gf0   = (const float*)d_in[7];
    const float* bf0   = (const float*)d_in[8];
    const float* W1    = (const float*)d_in[9];
    // d_in[10] = b1: provably cancels inside BN2 (mean subtraction) — unused.
    const float* g1    = (const float*)d_in[11];
    const float* beta1 = (const float*)d_in[12];
    float* out = (float*)d_out;

    k_init<<<1, 64>>>();
    k_stats1<<<1184, 128>>>(xyz, pts, gidx, Wl0, Wf0);
    k_fold<<<1, 32>>>(Wl0, gl0, bl0, Wf0, gf0, bf0);
    k_main<<<592, 128>>>(xyz, pts, gidx, W1);
    k_final<<<(NPTS * 64 + 255) / 256, 256>>>(g1, beta1, out);
}

// round 4
// speedup vs baseline: 1.0064x; 1.0064x over previous
#include <cuda_runtime.h>
#include <cfloat>

// Problem constants
#define NPTS    65536
#define KNB     32
#define CNT_INV (1.0f / 2097152.0f)   // 1/(N*K), exact power of two
#define BN_EPS  1e-5f

// ---------------- scratch (__device__ globals: no allocation allowed) ----------------
__device__ float g_sL[32], g_qL[32], g_sF[32], g_qF[32];   // layer1 pre-BN channel stats
__device__ float g_wl[32 * 3];                              // folded layer1 xyz weights
__device__ float g_wf[32 * 16];                             // folded layer1 feat weights
__device__ float g_bh[32];                                  // folded layer1 bias
__device__ float g_s2[64], g_q2[64];                        // layer2 pre-BN channel stats
__device__ float g_zmax[NPTS * 64];                         // per-(n,o) max_k z  (pre-BN)
__device__ float g_zmin[NPTS * 64];                         // per-(n,o) min_k z  (pre-BN)

// ---------------- packed f32x2 FMA (guarded: sm_100+ only, scalar fallback) ----------------
__device__ __forceinline__ void ffma2(float2& acc, float2 a, float2 b) {
#if defined(__CUDA_ARCH__) && (__CUDA_ARCH__ >= 1000)
    union F2U { float2 f; unsigned long long u; };
    F2U A, B, C; A.f = a; B.f = b; C.f = acc;
    asm("fma.rn.f32x2 %0, %1, %2, %0;" : "+l"(C.u) : "l"(A.u), "l"(B.u));
    acc = C.f;
#else
    acc.x = fmaf(a.x, b.x, acc.x);
    acc.y = fmaf(a.y, b.y, acc.y);
#endif
}

// ---------------- kernel 0: zero the stat accumulators (fresh every launch) ----------------
__global__ void k_init() {
    const int t = threadIdx.x;   // 64 threads
    if (t < 32) { g_sL[t] = 0.f; g_qL[t] = 0.f; g_sF[t] = 0.f; g_qF[t] = 0.f; }
    g_s2[t] = 0.f; g_q2[t] = 0.f;
}

// ---------------- kernel 1: layer-1 pre-BN channel statistics ----------------
// One warp processes points sequentially; lane = hidden channel o in [0,32).
// Inputs for each (n,k) sample are same-address broadcast loads (L2-resident).
__global__ __launch_bounds__(128)
void k_stats1(const float* __restrict__ xyz, const float* __restrict__ pts,
              const int* __restrict__ gidx,
              const float* __restrict__ Wl0, const float* __restrict__ Wf0) {
    const int lane  = threadIdx.x & 31;
    const int warp  = blockIdx.x * (blockDim.x >> 5) + (threadIdx.x >> 5);
    const int nwarp = gridDim.x * (blockDim.x >> 5);

    const float wl0 = Wl0[lane * 3 + 0];
    const float wl1 = Wl0[lane * 3 + 1];
    const float wl2 = Wl0[lane * 3 + 2];
    float wf[16];
#pragma unroll
    for (int c = 0; c < 16; c++) wf[c] = Wf0[lane * 16 + c];

    float sL = 0.f, qL = 0.f, sF = 0.f, qF = 0.f;

    for (int n = warp; n < NPTS; n += nwarp) {
        const int   gi = gidx[n * KNB + lane];          // coalesced
        const float c0 = __ldg(&xyz[n * 3 + 0]);
        const float c1 = __ldg(&xyz[n * 3 + 1]);
        const float c2 = __ldg(&xyz[n * 3 + 2]);
#pragma unroll 2
        for (int k = 0; k < KNB; k++) {
            const int g = __shfl_sync(0xffffffffu, gi, k);
            const float d0 = __ldg(&xyz[g * 3 + 0]) - c0;
            const float d1 = __ldg(&xyz[g * 3 + 1]) - c1;
            const float d2 = __ldg(&xyz[g * 3 + 2]) - c2;
            const float4* pr = (const float4*)pts + (size_t)g * 4;
            const float4 p0 = __ldg(pr + 0), p1 = __ldg(pr + 1);
            const float4 p2 = __ldg(pr + 2), p3 = __ldg(pr + 3);

            float loc = wl0 * d0; loc = fmaf(wl1, d1, loc); loc = fmaf(wl2, d2, loc);

            float ft = wf[0] * p0.x;
            ft = fmaf(wf[1],  p0.y, ft); ft = fmaf(wf[2],  p0.z, ft); ft = fmaf(wf[3],  p0.w, ft);
            ft = fmaf(wf[4],  p1.x, ft); ft = fmaf(wf[5],  p1.y, ft); ft = fmaf(wf[6],  p1.z, ft);
            ft = fmaf(wf[7],  p1.w, ft); ft = fmaf(wf[8],  p2.x, ft); ft = fmaf(wf[9],  p2.y, ft);
            ft = fmaf(wf[10], p2.z, ft); ft = fmaf(wf[11], p2.w, ft); ft = fmaf(wf[12], p3.x, ft);
            ft = fmaf(wf[13], p3.y, ft); ft = fmaf(wf[14], p3.z, ft); ft = fmaf(wf[15], p3.w, ft);

            sL += loc; qL = fmaf(loc, loc, qL);
            sF += ft;  qF = fmaf(ft,  ft,  qF);
        }
    }
    atomicAdd(&g_sL[lane], sL); atomicAdd(&g_qL[lane], qL);
    atomicAdd(&g_sF[lane], sF); atomicAdd(&g_qF[lane], qF);
}

// ---------------- kernel 2: fold BN1 into layer-1 weights ----------------
__global__ void k_fold(const float* __restrict__ Wl0, const float* __restrict__ gl0,
                       const float* __restrict__ bl0, const float* __restrict__ Wf0,
                       const float* __restrict__ gf0, const float* __restrict__ bf0) {
    const int i = threadIdx.x;
    if (i >= 32) return;
    const float mL = g_sL[i] * CNT_INV;
    const float vL = fmaxf(g_qL[i] * CNT_INV - mL * mL, 0.f);
    const float sL = gl0[i] * rsqrtf(vL + BN_EPS);
    const float mF = g_sF[i] * CNT_INV;
    const float vF = fmaxf(g_qF[i] * CNT_INV - mF * mF, 0.f);
    const float sF = gf0[i] * rsqrtf(vF + BN_EPS);
#pragma unroll
    for (int c = 0; c < 3; c++)  g_wl[i * 3 + c]  = sL * Wl0[i * 3 + c];
#pragma unroll
    for (int c = 0; c < 16; c++) g_wf[i * 16 + c] = sF * Wf0[i * 16 + c];
    g_bh[i] = bl0[i] - sL * mL + bf0[i] - sF * mF;
}

// ---------------- kernel 3: main fused pass ----------------
// One warp per point n. Layer 1: lane = hidden channel i (folded weights in
// registers, neighbor data broadcast). Layer 2: lane = output channels
// (lane, lane+32) with packed f32x2 FMA over hidden-channel pairs via shuffles.
// Stores per-(n,o) zmax/zmin (pre-BN2), accumulates global sum / sumsq of z.
__global__ __launch_bounds__(128, 4)
void k_main(const float* __restrict__ xyz, const float* __restrict__ pts,
            const int* __restrict__ gidx, const float* __restrict__ W1) {
    const int lane  = threadIdx.x & 31;
    const int warp  = blockIdx.x * (blockDim.x >> 5) + (threadIdx.x >> 5);
    const int nwarp = gridDim.x * (blockDim.x >> 5);

    // layer-1 folded weights, lane = hidden channel
    const float wl0 = g_wl[lane * 3 + 0];
    const float wl1 = g_wl[lane * 3 + 1];
    const float wl2 = g_wl[lane * 3 + 2];
    float wf[16];
#pragma unroll
    for (int c = 0; c < 16; c++) wf[c] = g_wf[lane * 16 + c];
    const float bh = g_bh[lane];

    // layer-2 weights, lane = (o, o+32), packed over hidden-channel pairs
    float2 wA[16], wB[16];
    {
        const float2* rA = (const float2*)(W1 + lane * 32);
        const float2* rB = (const float2*)(W1 + (lane + 32) * 32);
#pragma unroll
        for (int t = 0; t < 16; t++) { wA[t] = __ldg(rA + t); wB[t] = __ldg(rB + t); }
    }

    float sumA = 0.f, sqA = 0.f, sumB = 0.f, sqB = 0.f;

    for (int n = warp; n < NPTS; n += nwarp) {
        const int   gi = gidx[n * KNB + lane];          // coalesced
        const float c0 = __ldg(&xyz[n * 3 + 0]);
        const float c1 = __ldg(&xyz[n * 3 + 1]);
        const float c2 = __ldg(&xyz[n * 3 + 2]);

        float maxA = -FLT_MAX, minA = FLT_MAX, maxB = -FLT_MAX, minB = FLT_MAX;

#pragma unroll 2
        for (int k = 0; k < KNB; k++) {
            const int g = __shfl_sync(0xffffffffu, gi, k);
            const float d0 = __ldg(&xyz[g * 3 + 0]) - c0;
            const float d1 = __ldg(&xyz[g * 3 + 1]) - c1;
            const float d2 = __ldg(&xyz[g * 3 + 2]) - c2;
            const float4* pr = (const float4*)pts + (size_t)g * 4;
            const float4 p0 = __ldg(pr + 0), p1 = __ldg(pr + 1);
            const float4 p2 = __ldg(pr + 2), p3 = __ldg(pr + 3);

            float h = bh;
            h = fmaf(wl0, d0, h); h = fmaf(wl1, d1, h); h = fmaf(wl2, d2, h);
            h = fmaf(wf[0],  p0.x, h); h = fmaf(wf[1],  p0.y, h);
            h = fmaf(wf[2],  p0.z, h); h = fmaf(wf[3],  p0.w, h);
            h = fmaf(wf[4],  p1.x, h); h = fmaf(wf[5],  p1.y, h);
            h = fmaf(wf[6],  p1.z, h); h = fmaf(wf[7],  p1.w, h);
            h = fmaf(wf[8],  p2.x, h); h = fmaf(wf[9],  p2.y, h);
            h = fmaf(wf[10], p2.z, h); h = fmaf(wf[11], p2.w, h);
            h = fmaf(wf[12], p3.x, h); h = fmaf(wf[13], p3.y, h);
            h = fmaf(wf[14], p3.z, h); h = fmaf(wf[15], p3.w, h);
            h = fmaxf(h, 0.f);                           // ReLU(BN1(loc)+BN1(feat))

            // layer 2: z[o] = sum_i W1[o][i] * h[i]  (b1 cancels inside BN2)
            float2 zA = make_float2(0.f, 0.f);
            float2 zB = make_float2(0.f, 0.f);
#pragma unroll
            for (int t = 0; t < 16; t++) {
                float2 hv;
                hv.x = __shfl_sync(0xffffffffu, h, 2 * t);
                hv.y = __shfl_sync(0xffffffffu, h, 2 * t + 1);
                ffma2(zA, wA[t], hv);
                ffma2(zB, wB[t], hv);
            }
            const float za = zA.x + zA.y;
            const float zb = zB.x + zB.y;

            maxA = fmaxf(maxA, za); minA = fminf(minA, za);
            maxB = fmaxf(maxB, zb); minB = fminf(minB, zb);
            sumA += za; sqA = fmaf(za, za, sqA);
            sumB += zb; sqB = fmaf(zb, zb, sqB);
        }

        g_zmax[n * 64 + lane]      = maxA;
        g_zmax[n * 64 + 32 + lane] = maxB;
        g_zmin[n * 64 + lane]      = minA;
        g_zmin[n * 64 + 32 + lane] = minB;
    }

    atomicAdd(&g_s2[lane],      sumA); atomicAdd(&g_q2[lane],      sqA);
    atomicAdd(&g_s2[lane + 32], sumB); atomicAdd(&g_q2[lane + 32], sqB);
}

// ---------------- kernel 4: finalize ----------------
// out[n,o] = relu(s2*(z* - m2) + beta2), z* = (s2>=0 ? zmax : zmin)  (monotone trick)
__global__ __launch_bounds__(256)
void k_final(const float* __restrict__ g1, const float* __restrict__ beta1,
             float* __restrict__ out) {
    const int idx = blockIdx.x * blockDim.x + threadIdx.x;
    if (idx >= NPTS * 64) return;
    const int o = idx & 63;
    const float m = g_s2[o] * CNT_INV;
    const float v = fmaxf(g_q2[o] * CNT_INV - m * m, 0.f);
    const float s = g1[o] * rsqrtf(v + BN_EPS);
    const float c = beta1[o] - s * m;
    const float z = (s >= 0.f) ? g_zmax[idx] : g_zmin[idx];
    out[idx] = fmaxf(fmaf(s, z, c), 0.f);
}

// ---------------- launch ----------------
extern "C" void kernel_launch(void* const* d_in, const int* in_sizes, int n_in,
                              void* d_out, int out_size) {
    const float* xyz   = (const float*)d_in[0];
    const float* pts   = (const float*)d_in[1];
    const int*   gidx  = (const int*)  d_in[2];
    const float* Wl0   = (const float*)d_in[3];
    const float* gl0   = (const float*)d_in[4];
    const float* bl0   = (const float*)d_in[5];
    const float* Wf0   = (const float*)d_in[6];
    const float* gf0   = (const float*)d_in[7];
    const float* bf0   = (const float*)d_in[8];
    const float* W1    = (const float*)d_in[9];
    // d_in[10] = b1: provably cancels inside BN2 (mean subtraction) — unused.
    const float* g1    = (const float*)d_in[11];
    const float* beta1 = (const float*)d_in[12];
    float* out = (float*)d_out;

    k_init<<<1, 64>>>();
    k_stats1<<<1184, 128>>>(xyz, pts, gidx, Wl0, Wf0);
    k_fold<<<1, 32>>>(Wl0, gl0, bl0, Wf0, gf0, bf0);
    k_main<<<592, 128>>>(xyz, pts, gidx, W1);
    k_final<<<(NPTS * 64 + 255) / 256, 256>>>(g1, beta1, out);
}

// round 7
// speedup vs baseline: 1.4405x; 1.4314x over previous
#include <cuda_runtime.h>
#include <cfloat>

#define NPTS    65536
#define KNB     32
#define NSAMP   (NPTS * KNB)
#define CNT_INV (1.0f / 2097152.0f)
#define BN_EPS  1e-5f
#define GRID_MAIN 444

// g_acc float layout: C[9] | SG1[3] | SG2[6] | SN1[3] | SN2[6] | SF[32] | QF[32] | S2[64] | Q2[64]
#define OFF_C    0
#define OFF_SG1  9
#define OFF_SG2  12
#define OFF_SN1  18
#define OFF_SN2  21
#define OFF_SF   27
#define OFF_QF   59
#define OFF_S2   91
#define OFF_Q2   155
#define ACC_SZ   219

__device__ float  g_acc[ACC_SZ];
__device__ int    g_cnt[NPTS];
__device__ float  g_zmax[NPTS * 64];
__device__ float  g_zmin[NPTS * 64];
__device__ float4 g_stage1[160];            // layer1 folded weights, [i][5 float4] = 10 (w,w') pairs
__device__ float2 g_stage2[1024];           // layer2 weights, [i*32+l] = (W1[2l][i], W1[2l+1][i])

__device__ __forceinline__ void ffma2(float2& acc, float2 a, float2 b) {
#if defined(__CUDA_ARCH__) && (__CUDA_ARCH__ >= 1000)
    union { float2 f; unsigned long long u; } A, B, C;
    A.f = a; B.f = b; C.f = acc;
    asm("fma.rn.f32x2 %0, %1, %2, %0;" : "+l"(C.u) : "l"(A.u), "l"(B.u));
    acc = C.f;
#else
    acc.x = fmaf(a.x, b.x, acc.x);
    acc.y = fmaf(a.y, b.y, acc.y);
#endif
}

// ---------------- kernel 0: zero accumulators + histogram ----------------
__global__ void k_init() {
    const int t = blockIdx.x * blockDim.x + threadIdx.x;
    if (t < NPTS) g_cnt[t] = 0;
    if (t < ACC_SZ) g_acc[t] = 0.f;
}

// ---------------- kernel 1: histogram + cross term C = sum x_g x_n^T ----------------
__global__ __launch_bounds__(256)
void k_hc(const float* __restrict__ xyz, const int* __restrict__ gidx) {
    __shared__ float sC[9];
    const int tid = threadIdx.x;
    if (tid < 9) sC[tid] = 0.f;
    __syncthreads();

    const int t0     = blockIdx.x * blockDim.x + tid;
    const int stride = gridDim.x * blockDim.x;
    float C[9];
#pragma unroll
    for (int j = 0; j < 9; j++) C[j] = 0.f;

    for (int s = t0; s < NSAMP; s += stride) {
        const int g = gidx[s];
        atomicAdd(&g_cnt[g], 1);
        const int n = s >> 5;   // warp-uniform
        const float n0 = __ldg(&xyz[n * 3 + 0]);
        const float n1 = __ldg(&xyz[n * 3 + 1]);
        const float n2 = __ldg(&xyz[n * 3 + 2]);
        const float a0 = __ldg(&xyz[g * 3 + 0]);
        const float a1 = __ldg(&xyz[g * 3 + 1]);
        const float a2 = __ldg(&xyz[g * 3 + 2]);
        C[0] = fmaf(a0, n0, C[0]); C[1] = fmaf(a0, n1, C[1]); C[2] = fmaf(a0, n2, C[2]);
        C[3] = fmaf(a1, n0, C[3]); C[4] = fmaf(a1, n1, C[4]); C[5] = fmaf(a1, n2, C[5]);
        C[6] = fmaf(a2, n0, C[6]); C[7] = fmaf(a2, n1, C[7]); C[8] = fmaf(a2, n2, C[8]);
    }
#pragma unroll
    for (int j = 0; j < 9; j++)
#pragma unroll
        for (int o = 16; o > 0; o >>= 1) C[j] += __shfl_xor_sync(0xffffffffu, C[j], o);
    if ((tid & 31) == 0)
#pragma unroll
        for (int j = 0; j < 9; j++) atomicAdd(&sC[j], C[j]);
    __syncthreads();
    if (tid < 9) atomicAdd(&g_acc[OFF_C + tid], sC[tid]);
}

// ---------------- kernel 2: cnt-weighted moments over unique points ----------------
__global__ __launch_bounds__(256)
void k_mom(const float* __restrict__ xyz, const float* __restrict__ pts,
           const float* __restrict__ Wf0) {
    __shared__ float sA[82];
    const int tid = threadIdx.x;
    if (tid < 82) sA[tid] = 0.f;
    __syncthreads();

    const int g = blockIdx.x * blockDim.x + tid;   // exactly NPTS threads
    float a[82];
#pragma unroll
    for (int j = 0; j < 82; j++) a[j] = 0.f;

    if (g < NPTS) {
        const float w  = (float)g_cnt[g];
        const float x0 = xyz[g * 3 + 0], x1 = xyz[g * 3 + 1], x2 = xyz[g * 3 + 2];
        // sg1(0..2), sg2(3..8) as (00,01,02,11,12,22), sn1(9..11), sn2(12..17), sF(18..49), qF(50..81)
        a[0] = w * x0; a[1] = w * x1; a[2] = w * x2;
        a[3] = w * x0 * x0; a[4] = w * x0 * x1; a[5] = w * x0 * x2;
        a[6] = w * x1 * x1; a[7] = w * x1 * x2; a[8] = w * x2 * x2;
        a[9] = x0; a[10] = x1; a[11] = x2;
        a[12] = x0 * x0; a[13] = x0 * x1; a[14] = x0 * x2;
        a[15] = x1 * x1; a[16] = x1 * x2; a[17] = x2 * x2;
        float p[16];
        const float4* pr = (const float4*)pts + (size_t)g * 4;
#pragma unroll
        for (int q = 0; q < 4; q++) {
            const float4 v = __ldg(pr + q);
            p[q * 4 + 0] = v.x; p[q * 4 + 1] = v.y; p[q * 4 + 2] = v.z; p[q * 4 + 3] = v.w;
        }
#pragma unroll
        for (int i = 0; i < 32; i++) {
            float f = 0.f;
#pragma unroll
            for (int c = 0; c < 16; c++) f = fmaf(__ldg(&Wf0[i * 16 + c]), p[c], f);
            a[18 + i] = w * f;
            a[50 + i] = w * f * f;
        }
    }
#pragma unroll
    for (int j = 0; j < 82; j++)
#pragma unroll
        for (int o = 16; o > 0; o >>= 1) a[j] += __shfl_xor_sync(0xffffffffu, a[j], o);
    if ((tid & 31) == 0)
#pragma unroll
        for (int j = 0; j < 82; j++) atomicAdd(&sA[j], a[j]);
    __syncthreads();
    if (tid < 82) atomicAdd(&g_acc[OFF_SG1 + tid], sA[tid]);
}

// ---------------- kernel 3: fold BN1, stage weights ----------------
// Symmetric 3x3 pack order: (0,0)=0 (0,1)=1 (0,2)=2 (1,1)=3 (1,2)=4 (2,2)=5
__device__ __forceinline__ int symi(int aa, int bb) {
    const int lo = min(aa, bb), hi = max(aa, bb);
    return (lo == 0) ? hi : ((lo == 1) ? (2 + hi) : 5);
}

__global__ void k_fold(const float* __restrict__ Wl0, const float* __restrict__ gl0,
                       const float* __restrict__ bl0, const float* __restrict__ Wf0,
                       const float* __restrict__ gf0, const float* __restrict__ bf0,
                       const float* __restrict__ W1) {
    const int t = threadIdx.x;   // 64 threads
    if (t < 32) {
        const int i = t;
        float T1[3], T2[3][3];
#pragma unroll
        for (int c = 0; c < 3; c++)
            T1[c] = g_acc[OFF_SG1 + c] - 32.f * g_acc[OFF_SN1 + c];
#pragma unroll
        for (int aa = 0; aa < 3; aa++)
#pragma unroll
            for (int bb = 0; bb < 3; bb++)
                T2[aa][bb] = g_acc[OFF_SG2 + symi(aa, bb)]
                           - g_acc[OFF_C + aa * 3 + bb] - g_acc[OFF_C + bb * 3 + aa]
                           + 32.f * g_acc[OFF_SN2 + symi(aa, bb)];
        const float wv[3] = {Wl0[i * 3 + 0], Wl0[i * 3 + 1], Wl0[i * 3 + 2]};
        const float mL = (wv[0] * T1[0] + wv[1] * T1[1] + wv[2] * T1[2]) * CNT_INV;
        float el2 = 0.f;
#pragma unroll
        for (int aa = 0; aa < 3; aa++)
#pragma unroll
            for (int bb = 0; bb < 3; bb++) el2 = fmaf(wv[aa] * wv[bb], T2[aa][bb], el2);
        el2 *= CNT_INV;
        const float vL = fmaxf(el2 - mL * mL, 0.f);
        const float sL = gl0[i] * rsqrtf(vL + BN_EPS);

        const float mF = g_acc[OFF_SF + i] * CNT_INV;
        const float vF = fmaxf(g_acc[OFF_QF + i] * CNT_INV - mF * mF, 0.f);
        const float sF = gf0[i] * rsqrtf(vF + BN_EPS);

        float w19[20];
#pragma unroll
        for (int c = 0; c < 3; c++)  w19[c]     = sL * wv[c];
#pragma unroll
        for (int c = 0; c < 16; c++) w19[3 + c] = sF * Wf0[i * 16 + c];
        w19[19] = bl0[i] - sL * mL + bf0[i] - sF * mF;   // bias paired with constant 1.0 input
        float2* s1 = (float2*)g_stage1;
#pragma unroll
        for (int j = 0; j < 10; j++)
            s1[i * 10 + j] = make_float2(w19[2 * j], w19[2 * j + 1]);
    }
    for (int j = t; j < 1024; j += 64) {
        const int i = j >> 5, l = j & 31;
        g_stage2[j] = make_float2(W1[(2 * l) * 32 + i], W1[(2 * l + 1) * 32 + i]);
    }
}

// ---------------- kernel 4: main fused pass ----------------
// Lane = neighbor k. L1 sample-major (weights via LDS broadcast, bias via const-1 pair),
// h staged duplicated+swizzled in smem, L2 channel-major with weights in registers,
// in-lane max/min/sum/sq over k. No shuffles in the hot loop.
__global__ __launch_bounds__(128, 3)
void k_main(const float* __restrict__ xyz, const float* __restrict__ pts,
            const int* __restrict__ gidx) {
    __shared__ float4 sw1[160];          // 2.5 KB
    __shared__ float  sh[4][32 * 72];    // 36.8 KB, per-warp dup'd h, row stride 72 floats
    const int lane = threadIdx.x & 31;
    const int wib  = threadIdx.x >> 5;

    for (int t = threadIdx.x; t < 160; t += 128) sw1[t] = g_stage1[t];
    __syncthreads();

    float2 w2r[32];
#pragma unroll
    for (int i = 0; i < 32; i++) w2r[i] = __ldg(&g_stage2[i * 32 + lane]);

    float* hrow = &sh[wib][lane * 72];
    const float* hbase = sh[wib];

    float2 stat_s = make_float2(0.f, 0.f), stat_q = make_float2(0.f, 0.f);

    const int warpid = blockIdx.x * 4 + wib;
    for (int n = warpid; n < NPTS; n += GRID_MAIN * 4) {
        const int g = gidx[n * KNB + lane];
        float2 x2[10];
        {
            const float c0 = __ldg(&xyz[n * 3 + 0]);
            const float c1 = __ldg(&xyz[n * 3 + 1]);
            const float c2 = __ldg(&xyz[n * 3 + 2]);
            const float d0 = __ldg(&xyz[g * 3 + 0]) - c0;
            const float d1 = __ldg(&xyz[g * 3 + 1]) - c1;
            const float d2 = __ldg(&xyz[g * 3 + 2]) - c2;
            const float4* pr = (const float4*)pts + (size_t)g * 4;
            const float4 p0 = __ldg(pr + 0), p1 = __ldg(pr + 1);
            const float4 p2 = __ldg(pr + 2), p3 = __ldg(pr + 3);
            x2[0] = make_float2(d0,   d1);
            x2[1] = make_float2(d2,   p0.x);
            x2[2] = make_float2(p0.y, p0.z);
            x2[3] = make_float2(p0.w, p1.x);
            x2[4] = make_float2(p1.y, p1.z);
            x2[5] = make_float2(p1.w, p2.x);
            x2[6] = make_float2(p2.y, p2.z);
            x2[7] = make_float2(p2.w, p3.x);
            x2[8] = make_float2(p3.y, p3.z);
            x2[9] = make_float2(p3.w, 1.f);          // constant-1 slot carries the bias
        }

        // layer 1: h[i] for i=0..31, stored duplicated with granule swizzle
#pragma unroll
        for (int i2 = 0; i2 < 16; i2++) {
            float h[2];
#pragma unroll
            for (int u = 0; u < 2; u++) {
                const int i = 2 * i2 + u;
                float2 acc = make_float2(0.f, 0.f);
#pragma unroll
                for (int q = 0; q < 5; q++) {
                    const float4 w = sw1[i * 5 + q];
                    ffma2(acc, make_float2(w.x, w.y), x2[2 * q]);
                    ffma2(acc, make_float2(w.z, w.w), x2[2 * q + 1]);
                }
                h[u] = fmaxf(acc.x + acc.y, 0.f);
            }
            const int c = (i2 + lane) & 15;
            *(float4*)(hrow + c * 4) = make_float4(h[0], h[0], h[1], h[1]);
        }
        __syncwarp();

        // layer 2: lane owns outputs (2l, 2l+1); weights in regs; h via broadcast LDS.128
        float2 maxv = make_float2(-FLT_MAX, -FLT_MAX);
        float2 minv = make_float2( FLT_MAX,  FLT_MAX);
#pragma unroll 2
        for (int k = 0; k < KNB; k++) {
            const float* hr = hbase + k * 72;
            float2 z = make_float2(0.f, 0.f);
#pragma unroll
            for (int j = 0; j < 16; j++) {
                const float4 q = *(const float4*)(hr + (((j + k) & 15) * 4));
                ffma2(z, w2r[2 * j],     make_float2(q.x, q.y));
                ffma2(z, w2r[2 * j + 1], make_float2(q.z, q.w));
            }
            maxv.x = fmaxf(maxv.x, z.x); maxv.y = fmaxf(maxv.y, z.y);
            minv.x = fminf(minv.x, z.x); minv.y = fminf(minv.y, z.y);
            stat_s.x += z.x; stat_s.y += z.y;
            ffma2(stat_q, z, z);
        }
        __syncwarp();

        ((float2*)(g_zmax + (size_t)n * 64))[lane] = maxv;
        ((float2*)(g_zmin + (size_t)n * 64))[lane] = minv;
    }
    atomicAdd(&g_acc[OFF_S2 + 2 * lane],     stat_s.x);
    atomicAdd(&g_acc[OFF_S2 + 2 * lane + 1], stat_s.y);
    atomicAdd(&g_acc[OFF_Q2 + 2 * lane],     stat_q.x);
    atomicAdd(&g_acc[OFF_Q2 + 2 * lane + 1], stat_q.y);
}

// ---------------- kernel 5: finalize ----------------
__global__ __launch_bounds__(256)
void k_final(const float* __restrict__ g1, const float* __restrict__ beta1,
             float* __restrict__ out) {
    const int idx = blockIdx.x * blockDim.x + threadIdx.x;
    if (idx >= NPTS * 64) return;
    const int o = idx & 63;
    const float m = g_acc[OFF_S2 + o] * CNT_INV;
    const float v = fmaxf(g_acc[OFF_Q2 + o] * CNT_INV - m * m, 0.f);
    const float s = g1[o] * rsqrtf(v + BN_EPS);
    const float c = beta1[o] - s * m;
    const float z = (s >= 0.f) ? g_zmax[idx] : g_zmin[idx];
    out[idx] = fmaxf(fmaf(s, z, c), 0.f);
}

// ---------------- launch ----------------
extern "C" void kernel_launch(void* const* d_in, const int* in_sizes, int n_in,
                              void* d_out, int out_size) {
    const float* xyz   = (const float*)d_in[0];
    const float* pts   = (const float*)d_in[1];
    const int*   gidx  = (const int*)  d_in[2];
    const float* Wl0   = (const float*)d_in[3];
    const float* gl0   = (const float*)d_in[4];
    const float* bl0   = (const float*)d_in[5];
    const float* Wf0   = (const float*)d_in[6];
    const float* gf0   = (const float*)d_in[7];
    const float* bf0   = (const float*)d_in[8];
    const float* W1    = (const float*)d_in[9];
    // d_in[10] = b1: cancels inside BN2 (mean subtraction) — unused.
    const float* g1    = (const float*)d_in[11];
    const float* beta1 = (const float*)d_in[12];
    float* out = (float*)d_out;

    k_init<<<NPTS / 256, 256>>>();
    k_hc<<<512, 256>>>(xyz, gidx);
    k_mom<<<NPTS / 256, 256>>>(xyz, pts, Wf0);
    k_fold<<<1, 64>>>(Wl0, gl0, bl0, Wf0, gf0, bf0, W1);
    k_main<<<GRID_MAIN, 128>>>(xyz, pts, gidx);
    k_final<<<(NPTS * 64 + 255) / 256, 256>>>(g1, beta1, out);
}